// round 5
// baseline (speedup 1.0000x reference)
#include <cuda_runtime.h>
#include <math.h>
#include <stdint.h>

#define Bx 2
#define Tx 2048
#define Hx 2560
#define NHx 8
#define NKVx 4
#define Dx 256
#define WINDOWx 1024
#define NTOK (Bx*Tx)      /* 4096 */
#define QSTR (NHx*Dx)     /* 2048 */
#define KSTR (NKVx*Dx)    /* 1024 */

// ---------------- scratch (device globals; no allocation allowed) -----------
__device__ float g_q[NTOK*QSTR];
__device__ float g_k[NTOK*KSTR];
__device__ float g_v[NTOK*KSTR];
__device__ float g_att[NTOK*QSTR];
__device__ float g_pos[NTOK];

// ---------------- helpers ---------------------------------------------------
__device__ __forceinline__ uint32_t f2b(float x){ return __float_as_uint(x); }
__device__ __forceinline__ float tf32r(float x){
    uint32_t u; asm("cvt.rna.tf32.f32 %0, %1;" : "=r"(u) : "f"(x));
    return __uint_as_float(u);
}
__device__ __forceinline__ uint32_t tf32b(float x){
    uint32_t u; asm("cvt.rna.tf32.f32 %0, %1;" : "=r"(u) : "f"(x));
    return u;
}
__device__ __forceinline__ void mma8(float c[4], uint32_t a0, uint32_t a1,
                                     uint32_t a2, uint32_t a3,
                                     uint32_t b0, uint32_t b1){
    asm volatile("mma.sync.aligned.m16n8k8.row.col.f32.tf32.tf32.f32 "
                 "{%0,%1,%2,%3},{%4,%5,%6,%7},{%8,%9},{%0,%1,%2,%3};"
                 : "+f"(c[0]),"+f"(c[1]),"+f"(c[2]),"+f"(c[3])
                 : "r"(a0),"r"(a1),"r"(a2),"r"(a3),"r"(b0),"r"(b1));
}
__device__ __forceinline__ void cpa16(uint32_t dst, const float* src){
    asm volatile("cp.async.cg.shared.global [%0], [%1], 16;\n" :: "r"(dst), "l"(src));
}
#define CP_COMMIT() asm volatile("cp.async.commit_group;\n")
#define CP_WAIT0()  asm volatile("cp.async.wait_group 0;\n")
#define CP_WAIT1()  asm volatile("cp.async.wait_group 1;\n")
__device__ __forceinline__ uint32_t cvta_s(const void* p){
    return (uint32_t)__cvta_generic_to_shared(p);
}

// ---------------- position kernel ------------------------------------------
__global__ void pos_kernel(const int* __restrict__ seg, const int* __restrict__ cur,
                           float* __restrict__ pos)
{
    const int b = blockIdx.x;
    const int tid = threadIdx.x;
    const int* row = seg + b*Tx;
    __shared__ int sv[256], si[256];
    int bestv = -2147483647, besti = 0;
    for (int t = tid; t < Tx; t += 256) {
        int v = row[t];
        if (v > bestv) { bestv = v; besti = t; }
    }
    sv[tid] = bestv; si[tid] = besti;
    __syncthreads();
    for (int s = 128; s > 0; s >>= 1) {
        if (tid < s) {
            int v2 = sv[tid+s], i2 = si[tid+s];
            if (v2 > sv[tid] || (v2 == sv[tid] && i2 < si[tid])) { sv[tid] = v2; si[tid] = i2; }
        }
        __syncthreads();
    }
    const int amax = si[0];
    const int ci = (cur != nullptr) ? cur[0] : 0;
    for (int t = tid; t < Tx; t += 256) {
        long long p = (row[t] != 0) ? (long long)(t - amax) : (long long)1073741824;
        pos[b*Tx + t] = (float)(p + ci);
    }
}

// ---------------- RMSNorm + RoPE (outputs rounded to tf32) ------------------
__global__ __launch_bounds__(128)
void normrope_kernel(float* __restrict__ data, const float* __restrict__ scale,
                     const float* __restrict__ pos, int stride)
{
    const int token = blockIdx.x;
    const int h = blockIdx.y;
    const int tid = threadIdx.x;
    float* p = data + (size_t)token*stride + h*Dx;
    float a = p[tid];
    float b = p[tid + 128];
    float v2 = a*a + b*b;
    #pragma unroll
    for (int m = 16; m > 0; m >>= 1) v2 += __shfl_xor_sync(0xffffffffu, v2, m);
    __shared__ float red[4];
    if ((tid & 31) == 0) red[tid >> 5] = v2;
    __syncthreads();
    float total = red[0] + red[1] + red[2] + red[3];
    float inv = rsqrtf(total * (1.0f/256.0f) + 1e-6f);
    float an = a * inv * (1.0f + scale[tid]);
    float bn = b * inv * (1.0f + scale[tid + 128]);
    float posv = pos[token];
    float frac = (float)tid * (1.0f/128.0f);
    float freq = exp2f(-frac * 13.287712379549449f);
    float ang = posv * freq;
    float s, c;
    sincosf(ang, &s, &c);
    p[tid]       = tf32r(an*c - bn*s);
    p[tid + 128] = tf32r(bn*c + an*s);
}

// ---------------- tf32 tensor-core GEMM body 128x128x32 ---------------------
// A row-major (ldA=K), B row-major KxNB, C row-major (ldC=NC).
// Fragments rounded to tf32 (RNA) at smem->RF load, so raw f32 inputs are fine.
#define GASTR 36
#define GBSTR 136
#define GEMM_SMEM ((2*128*GASTR + 2*32*GBSTR)*4)

__device__ __forceinline__
void gemm_body(const float* __restrict__ A, const float* __restrict__ B,
               float* __restrict__ C, int K, int NB, int NC, int roundC,
               int m_blk, int nB, int nC, float* gsm)
{
    float* As = gsm;
    float* Bs = gsm + 2*128*GASTR;
    const int tid = threadIdx.x;
    const int warp = tid >> 5, lane = tid & 31;
    const int wm = warp >> 2, wn = warp & 3;
    const int l4 = lane >> 2, lk = lane & 3;
    const float* Ag = A + (size_t)m_blk * K;
    const float* Bg = B + nB;

    float c[4][4][4];
    #pragma unroll
    for (int i = 0; i < 4; i++)
        #pragma unroll
        for (int j = 0; j < 4; j++)
            #pragma unroll
            for (int r = 0; r < 4; r++) c[i][j][r] = 0.f;

    const int KT = K >> 5;

    auto load_stage = [&](int kt, int s){
        float* as = As + s*(128*GASTR);
        float* bs = Bs + s*(32*GBSTR);
        const int k0 = kt*32;
        #pragma unroll
        for (int i = 0; i < 4; i++){
            int r = (tid>>3) + i*32;
            cpa16(cvta_s(as + r*GASTR + (tid&7)*4), Ag + (size_t)r*K + k0 + (tid&7)*4);
        }
        #pragma unroll
        for (int i = 0; i < 4; i++){
            int r = (tid>>5) + i*8;
            cpa16(cvta_s(bs + r*GBSTR + (tid&31)*4), Bg + (size_t)(k0+r)*NB + (tid&31)*4);
        }
        CP_COMMIT();
    };

    load_stage(0, 0);
    for (int kt = 0; kt < KT; kt++){
        const int s = kt & 1;
        if (kt + 1 < KT){ load_stage(kt+1, s^1); CP_WAIT1(); }
        else            { CP_WAIT0(); }
        __syncthreads();
        const float* as = As + s*(128*GASTR);
        const float* bs = Bs + s*(32*GBSTR);
        #pragma unroll
        for (int kk = 0; kk < 4; kk++){
            uint32_t af[4][4], bf[4][2];
            const int kb = kk*8;
            #pragma unroll
            for (int mt = 0; mt < 4; mt++){
                const float* ap = as + (wm*64 + mt*16 + l4)*GASTR + kb + lk;
                af[mt][0] = tf32b(ap[0]);
                af[mt][1] = tf32b(ap[8*GASTR]);
                af[mt][2] = tf32b(ap[4]);
                af[mt][3] = tf32b(ap[8*GASTR+4]);
            }
            #pragma unroll
            for (int nt = 0; nt < 4; nt++){
                const float* bp = bs + (kb + lk)*GBSTR + wn*32 + nt*8 + l4;
                bf[nt][0] = tf32b(bp[0]);
                bf[nt][1] = tf32b(bp[4*GBSTR]);
            }
            #pragma unroll
            for (int mt = 0; mt < 4; mt++)
                #pragma unroll
                for (int nt = 0; nt < 4; nt++)
                    mma8(c[mt][nt], af[mt][0],af[mt][1],af[mt][2],af[mt][3],
                         bf[nt][0], bf[nt][1]);
        }
        __syncthreads();
    }

    #pragma unroll
    for (int mt = 0; mt < 4; mt++){
        const size_t r0 = (size_t)m_blk + wm*64 + mt*16 + l4;
        #pragma unroll
        for (int nt = 0; nt < 4; nt++){
            const size_t cc = (size_t)nC + wn*32 + nt*8 + lk*2;
            float2 v0 = make_float2(c[mt][nt][0], c[mt][nt][1]);
            float2 v1 = make_float2(c[mt][nt][2], c[mt][nt][3]);
            if (roundC){
                v0.x = tf32r(v0.x); v0.y = tf32r(v0.y);
                v1.x = tf32r(v1.x); v1.y = tf32r(v1.y);
            }
            *(float2*)(C + r0*NC + cc)     = v0;
            *(float2*)(C + (r0+8)*NC + cc) = v1;
        }
    }
}

// fused QKV projection: grid.x = 32 column-blocks over [Wq|Wk|Wv]
__global__ __launch_bounds__(256)
void gemm_qkv(const float* __restrict__ x,
              const float* __restrict__ Wq, const float* __restrict__ Wk,
              const float* __restrict__ Wv,
              float* __restrict__ q, float* __restrict__ k, float* __restrict__ v)
{
    extern __shared__ float gsm[];
    const int bxi = blockIdx.x;
    const int m_blk = blockIdx.y * 128;
    if (bxi < 16)
        gemm_body(x, Wq, q, Hx, QSTR, QSTR, 0, m_blk, bxi*128, bxi*128, gsm);
    else if (bxi < 24)
        gemm_body(x, Wk, k, Hx, KSTR, KSTR, 0, m_blk, (bxi-16)*128, (bxi-16)*128, gsm);
    else
        gemm_body(x, Wv, v, Hx, KSTR, KSTR, 1, m_blk, (bxi-24)*128, (bxi-24)*128, gsm);
}

// output projection
__global__ __launch_bounds__(256)
void gemm_wo(const float* __restrict__ att, const float* __restrict__ Wo,
             float* __restrict__ out)
{
    extern __shared__ float gsm[];
    gemm_body(att, Wo, out, QSTR, Hx, Hx, 0, blockIdx.y*128, blockIdx.x*128,
              blockIdx.x*128, gsm);
}

// ---------------- tf32 flash attention (512 threads) ------------------------
#define AQS 260   /* Q / K smem row stride */
#define AVS 264   /* V smem row stride */
#define APS 68    /* P smem row stride */
#define ATT_SMEM ((64*AQS + 64*AQS + 64*AVS + 64*APS + 3*64)*4)

__global__ __launch_bounds__(512)
void attn_tf32(const float* __restrict__ Q, const float* __restrict__ Kc,
               const float* __restrict__ Vc, float* __restrict__ O)
{
    extern __shared__ float att_sm[];
    float* sQ  = att_sm;
    float* sK  = sQ  + 64*AQS;
    float* sV  = sK  + 64*AQS;
    float* sP  = sV  + 64*AVS;
    float* sM  = sP  + 64*APS;
    float* sL  = sM  + 64;
    float* sAl = sL  + 64;

    const int tid = threadIdx.x, warp = tid >> 5, lane = tid & 31;
    const int l4 = lane >> 2, lk = lane & 3;
    const int qt = blockIdx.x, h = blockIdx.y, b = blockIdx.z;
    const int q0 = qt * 64, kvh = h >> 1;
    const float* Qb = Q  + (size_t)(b*Tx)*QSTR + h*Dx;
    const float* Kb = Kc + (size_t)(b*Tx)*KSTR + kvh*Dx;
    const float* Vb = Vc + (size_t)(b*Tx)*KSTR + kvh*Dx;

    // Q tile (64 x 256) via cp.async
    #pragma unroll
    for (int i = 0; i < 8; i++){
        int idx = tid + i*512;
        int r = idx >> 6, c4 = idx & 63;
        cpa16(cvta_s(sQ + r*AQS + c4*4), Qb + (size_t)(q0+r)*QSTR + c4*4);
    }
    CP_COMMIT();
    if (tid < 64){ sM[tid] = -1e30f; sL[tid] = 0.f; }

    const int kt0 = (qt > 16) ? qt - 16 : 0;

    // prologue K load
    #pragma unroll
    for (int i = 0; i < 8; i++){
        int idx = tid + i*512;
        int r = idx >> 6, c4 = idx & 63;
        cpa16(cvta_s(sK + r*AQS + c4*4), Kb + (size_t)(kt0*64+r)*KSTR + c4*4);
    }
    CP_COMMIT();

    const int wms = warp >> 2, wns = warp & 3;   // S grid: 4m x 4n (warp 16x16)
    const int wmp = warp >> 3, wnp = warp & 7;   // PV grid: 2m x 8n (warp 32x32)

    float o[2][4][4];
    #pragma unroll
    for (int i = 0; i < 2; i++)
        #pragma unroll
        for (int j = 0; j < 4; j++)
            #pragma unroll
            for (int r = 0; r < 4; r++) o[i][j][r] = 0.f;

    for (int kt = kt0; kt <= qt; kt++){
        CP_WAIT0();
        __syncthreads();         // K(kt) + Q ready; prev PV done with sP/sV

        // ---- S = Q K^T ----
        float s[2][4];
        #pragma unroll
        for (int nt = 0; nt < 2; nt++)
            #pragma unroll
            for (int r = 0; r < 4; r++) s[nt][r] = 0.f;

        #pragma unroll 4
        for (int d8 = 0; d8 < 32; d8++){
            const float* ap = sQ + (wms*16 + l4)*AQS + d8*8 + lk;
            uint32_t a0 = f2b(ap[0]), a1 = f2b(ap[8*AQS]);
            uint32_t a2 = f2b(ap[4]), a3 = f2b(ap[8*AQS+4]);
            #pragma unroll
            for (int nt = 0; nt < 2; nt++){
                const float* bp = sK + (wns*16 + nt*8 + l4)*AQS + d8*8 + lk;
                mma8(s[nt], a0, a1, a2, a3, f2b(bp[0]), f2b(bp[4]));
            }
        }

        // mask + scale, store logits to sP
        #pragma unroll
        for (int nt = 0; nt < 2; nt++){
            const int cbase = wns*16 + nt*8 + lk*2;
            const int kg0 = kt*64 + cbase;
            #pragma unroll
            for (int half = 0; half < 2; half++){
                const int r  = wms*16 + l4 + half*8;
                const int qg = q0 + r;
                float2 v;
                v.x = (kg0   <= qg && qg - kg0     < WINDOWx) ? s[nt][half*2+0]*0.0625f : -1e30f;
                v.y = (kg0+1 <= qg && qg - (kg0+1) < WINDOWx) ? s[nt][half*2+1]*0.0625f : -1e30f;
                *(float2*)(sP + r*APS + cbase) = v;
            }
        }
        __syncthreads();         // sP complete; sK consumed; sV free (prev PV done)

        // V(kt) load (overlaps softmax)
        #pragma unroll
        for (int i = 0; i < 8; i++){
            int idx = tid + i*512;
            int r = idx >> 6, c4 = idx & 63;
            cpa16(cvta_s(sV + r*AVS + c4*4), Vb + (size_t)(kt*64+r)*KSTR + c4*4);
        }
        CP_COMMIT();
        const bool more = (kt < qt);
        if (more){
            // K(kt+1) load (overlaps softmax + PV)
            #pragma unroll
            for (int i = 0; i < 8; i++){
                int idx = tid + i*512;
                int r = idx >> 6, c4 = idx & 63;
                cpa16(cvta_s(sK + r*AQS + c4*4), Kb + (size_t)((kt+1)*64+r)*KSTR + c4*4);
            }
            CP_COMMIT();
        }

        // ---- online softmax: 8 threads per row, 8 cols each ----
        {
            const int row = tid >> 3;
            const int cg  = (tid & 7) * 8;
            float* pr = sP + row*APS + cg;
            float4 p0 = *(float4*)(pr + 0);
            float4 p1 = *(float4*)(pr + 4);
            float rm = fmaxf(fmaxf(fmaxf(p0.x,p0.y),fmaxf(p0.z,p0.w)),
                             fmaxf(fmaxf(p1.x,p1.y),fmaxf(p1.z,p1.w)));
            rm = fmaxf(rm, __shfl_xor_sync(0xffffffffu, rm, 1));
            rm = fmaxf(rm, __shfl_xor_sync(0xffffffffu, rm, 2));
            rm = fmaxf(rm, __shfl_xor_sync(0xffffffffu, rm, 4));
            const float mo = sM[row];
            const float mn = fmaxf(mo, rm);
            float rs = 0.f;
            #define AEXP(t) { t = (t > -1e29f) ? __expf(t - mn) : 0.f; rs += t; t = tf32r(t); }
            AEXP(p0.x); AEXP(p0.y); AEXP(p0.z); AEXP(p0.w);
            AEXP(p1.x); AEXP(p1.y); AEXP(p1.z); AEXP(p1.w);
            #undef AEXP
            *(float4*)(pr + 0) = p0;
            *(float4*)(pr + 4) = p1;
            rs += __shfl_xor_sync(0xffffffffu, rs, 1);
            rs += __shfl_xor_sync(0xffffffffu, rs, 2);
            rs += __shfl_xor_sync(0xffffffffu, rs, 4);
            if ((tid & 7) == 0){
                float al = __expf(mo - mn);
                sAl[row] = al;
                sL[row]  = sL[row]*al + rs;
                sM[row]  = mn;
            }
        }
        if (more) CP_WAIT1(); else CP_WAIT0();   // V(kt) done (K(kt+1) may fly)
        __syncthreads();                         // softmax + V visible

        // ---- O = alpha*O + P V ----
        const float a00 = sAl[wmp*32 + l4];
        const float a01 = sAl[wmp*32 + l4 + 8];
        const float a10 = sAl[wmp*32 + 16 + l4];
        const float a11 = sAl[wmp*32 + 16 + l4 + 8];
        #pragma unroll
        for (int nt = 0; nt < 4; nt++){
            o[0][nt][0]*=a00; o[0][nt][1]*=a00; o[0][nt][2]*=a01; o[0][nt][3]*=a01;
            o[1][nt][0]*=a10; o[1][nt][1]*=a10; o[1][nt][2]*=a11; o[1][nt][3]*=a11;
        }
        #pragma unroll
        for (int k8 = 0; k8 < 8; k8++){
            uint32_t af[2][4];
            #pragma unroll
            for (int mt = 0; mt < 2; mt++){
                const float* ap = sP + (wmp*32 + mt*16 + l4)*APS + k8*8 + lk;
                af[mt][0] = f2b(ap[0]);
                af[mt][1] = f2b(ap[8*APS]);
                af[mt][2] = f2b(ap[4]);
                af[mt][3] = f2b(ap[8*APS+4]);
            }
            #pragma unroll
            for (int nt = 0; nt < 4; nt++){
                const float* bp = sV + (k8*8 + lk)*AVS + wnp*32 + nt*8 + l4;
                uint32_t b0 = f2b(bp[0]), b1 = f2b(bp[4*AVS]);
                #pragma unroll
                for (int mt = 0; mt < 2; mt++)
                    mma8(o[mt][nt], af[mt][0],af[mt][1],af[mt][2],af[mt][3], b0, b1);
            }
        }
    }

    // epilogue: normalize, round to tf32 (feeds Wo GEMM), write
    #pragma unroll
    for (int mt = 0; mt < 2; mt++){
        const int r0 = wmp*32 + mt*16 + l4;
        const float i0 = 1.0f / sL[r0];
        const float i1 = 1.0f / sL[r0+8];
        float* Ob0 = O + (size_t)(b*Tx + q0 + r0)*QSTR + h*Dx;
        float* Ob1 = O + (size_t)(b*Tx + q0 + r0 + 8)*QSTR + h*Dx;
        #pragma unroll
        for (int nt = 0; nt < 4; nt++){
            const int cc = wnp*32 + nt*8 + lk*2;
            float2 v0 = make_float2(tf32r(o[mt][nt][0]*i0), tf32r(o[mt][nt][1]*i0));
            float2 v1 = make_float2(tf32r(o[mt][nt][2]*i1), tf32r(o[mt][nt][3]*i1));
            *(float2*)(Ob0 + cc) = v0;
            *(float2*)(Ob1 + cc) = v1;
        }
    }
}

// ---------------- launch -----------------------------------------------------
extern "C" void kernel_launch(void* const* d_in, const int* in_sizes, int n_in,
                              void* d_out, int out_size)
{
    const float* x  = (const float*)d_in[0];
    const float* Wq = (const float*)d_in[1];
    const float* Wk = (const float*)d_in[2];
    const float* Wv = (const float*)d_in[3];
    const float* Wo = (const float*)d_in[4];
    const float* qs = (const float*)d_in[5];
    const float* ks = (const float*)d_in[6];
    const int*  seg = (const int*)d_in[7];
    const int*  cur = (n_in > 9) ? (const int*)d_in[9] : nullptr;
    float* out = (float*)d_out;
    (void)in_sizes; (void)out_size;

    float *q, *k, *v, *att, *pos;
    cudaGetSymbolAddress((void**)&q,   g_q);
    cudaGetSymbolAddress((void**)&k,   g_k);
    cudaGetSymbolAddress((void**)&v,   g_v);
    cudaGetSymbolAddress((void**)&att, g_att);
    cudaGetSymbolAddress((void**)&pos, g_pos);

    cudaFuncSetAttribute(gemm_qkv, cudaFuncAttributeMaxDynamicSharedMemorySize, GEMM_SMEM);
    cudaFuncSetAttribute(gemm_wo,  cudaFuncAttributeMaxDynamicSharedMemorySize, GEMM_SMEM);
    cudaFuncSetAttribute(attn_tf32, cudaFuncAttributeMaxDynamicSharedMemorySize, ATT_SMEM);

    pos_kernel<<<Bx, 256>>>(seg, cur, pos);

    gemm_qkv<<<dim3(32, NTOK/128), 256, GEMM_SMEM>>>(x, Wq, Wk, Wv, q, k, v);

    normrope_kernel<<<dim3(NTOK, NHx),  128>>>(q, qs, pos, QSTR);
    normrope_kernel<<<dim3(NTOK, NKVx), 128>>>(k, ks, pos, KSTR);

    attn_tf32<<<dim3(Tx/64, NHx, Bx), 512, ATT_SMEM>>>(q, k, v, att);

    gemm_wo<<<dim3(Hx/128, NTOK/128), 256, GEMM_SMEM>>>(att, Wo, out);
}

// round 9
// speedup vs baseline: 1.0121x; 1.0121x over previous
#include <cuda_runtime.h>
#include <math.h>
#include <stdint.h>

#define Bx 2
#define Tx 2048
#define Hx 2560
#define NHx 8
#define NKVx 4
#define Dx 256
#define WINDOWx 1024
#define NTOK (Bx*Tx)      /* 4096 */
#define QSTR (NHx*Dx)     /* 2048 */
#define KSTR (NKVx*Dx)    /* 1024 */

// ---------------- scratch (device globals; no allocation allowed) -----------
__device__ float g_q[NTOK*QSTR];
__device__ float g_k[NTOK*KSTR];
__device__ float g_v[NTOK*KSTR];
__device__ float g_att[NTOK*QSTR];
__device__ float g_pos[NTOK];

// ---------------- helpers ---------------------------------------------------
__device__ __forceinline__ uint32_t f2b(float x){ return __float_as_uint(x); }
__device__ __forceinline__ float tf32r(float x){
    uint32_t u; asm("cvt.rna.tf32.f32 %0, %1;" : "=r"(u) : "f"(x));
    return __uint_as_float(u);
}
__device__ __forceinline__ uint32_t tf32b(float x){
    uint32_t u; asm("cvt.rna.tf32.f32 %0, %1;" : "=r"(u) : "f"(x));
    return u;
}
__device__ __forceinline__ void mma8(float c[4], uint32_t a0, uint32_t a1,
                                     uint32_t a2, uint32_t a3,
                                     uint32_t b0, uint32_t b1){
    asm volatile("mma.sync.aligned.m16n8k8.row.col.f32.tf32.tf32.f32 "
                 "{%0,%1,%2,%3},{%4,%5,%6,%7},{%8,%9},{%0,%1,%2,%3};"
                 : "+f"(c[0]),"+f"(c[1]),"+f"(c[2]),"+f"(c[3])
                 : "r"(a0),"r"(a1),"r"(a2),"r"(a3),"r"(b0),"r"(b1));
}
__device__ __forceinline__ void cpa16(uint32_t dst, const float* src){
    asm volatile("cp.async.cg.shared.global [%0], [%1], 16;\n" :: "r"(dst), "l"(src));
}
#define CP_COMMIT() asm volatile("cp.async.commit_group;\n")
#define CP_WAIT0()  asm volatile("cp.async.wait_group 0;\n")
#define CP_WAIT1()  asm volatile("cp.async.wait_group 1;\n")
__device__ __forceinline__ uint32_t cvta_s(const void* p){
    return (uint32_t)__cvta_generic_to_shared(p);
}

// ---------------- position kernel ------------------------------------------
__global__ void pos_kernel(const int* __restrict__ seg, const int* __restrict__ cur,
                           float* __restrict__ pos)
{
    const int b = blockIdx.x;
    const int tid = threadIdx.x;
    const int* row = seg + b*Tx;
    __shared__ int sv[256], si[256];
    int bestv = -2147483647, besti = 0;
    for (int t = tid; t < Tx; t += 256) {
        int v = row[t];
        if (v > bestv) { bestv = v; besti = t; }
    }
    sv[tid] = bestv; si[tid] = besti;
    __syncthreads();
    for (int s = 128; s > 0; s >>= 1) {
        if (tid < s) {
            int v2 = sv[tid+s], i2 = si[tid+s];
            if (v2 > sv[tid] || (v2 == sv[tid] && i2 < si[tid])) { sv[tid] = v2; si[tid] = i2; }
        }
        __syncthreads();
    }
    const int amax = si[0];
    const int ci = (cur != nullptr) ? cur[0] : 0;
    for (int t = tid; t < Tx; t += 256) {
        long long p = (row[t] != 0) ? (long long)(t - amax) : (long long)1073741824;
        pos[b*Tx + t] = (float)(p + ci);
    }
}

// ---------------- RMSNorm + RoPE (outputs rounded to tf32) ------------------
__global__ __launch_bounds__(128)
void normrope_kernel(float* __restrict__ data, const float* __restrict__ scale,
                     const float* __restrict__ pos, int stride)
{
    const int token = blockIdx.x;
    const int h = blockIdx.y;
    const int tid = threadIdx.x;
    float* p = data + (size_t)token*stride + h*Dx;
    float a = p[tid];
    float b = p[tid + 128];
    float v2 = a*a + b*b;
    #pragma unroll
    for (int m = 16; m > 0; m >>= 1) v2 += __shfl_xor_sync(0xffffffffu, v2, m);
    __shared__ float red[4];
    if ((tid & 31) == 0) red[tid >> 5] = v2;
    __syncthreads();
    float total = red[0] + red[1] + red[2] + red[3];
    float inv = rsqrtf(total * (1.0f/256.0f) + 1e-6f);
    float an = a * inv * (1.0f + scale[tid]);
    float bn = b * inv * (1.0f + scale[tid + 128]);
    float posv = pos[token];
    float frac = (float)tid * (1.0f/128.0f);
    float freq = exp2f(-frac * 13.287712379549449f);
    float ang = posv * freq;
    float s, c;
    sincosf(ang, &s, &c);
    p[tid]       = tf32r(an*c - bn*s);
    p[tid + 128] = tf32r(bn*c + an*s);
}

// ---------------- tf32 tensor-core GEMM body 128x128x32 ---------------------
// A row-major (ldA=K), B row-major KxNB, C row-major (ldC=NC).
// Fragments rounded to tf32 (RNA) at smem->RF load, so raw f32 inputs are fine.
#define GASTR 36
#define GBSTR 136
#define GEMM_SMEM ((2*128*GASTR + 2*32*GBSTR)*4)

__device__ __forceinline__
void gemm_body(const float* __restrict__ A, const float* __restrict__ B,
               float* __restrict__ C, int K, int NB, int NC, int roundC,
               int m_blk, int nB, int nC, float* gsm)
{
    float* As = gsm;
    float* Bs = gsm + 2*128*GASTR;
    const int tid = threadIdx.x;
    const int warp = tid >> 5, lane = tid & 31;
    const int wm = warp >> 2, wn = warp & 3;
    const int l4 = lane >> 2, lk = lane & 3;
    const float* Ag = A + (size_t)m_blk * K;
    const float* Bg = B + nB;

    float c[4][4][4];
    #pragma unroll
    for (int i = 0; i < 4; i++)
        #pragma unroll
        for (int j = 0; j < 4; j++)
            #pragma unroll
            for (int r = 0; r < 4; r++) c[i][j][r] = 0.f;

    const int KT = K >> 5;

    auto load_stage = [&](int kt, int s){
        float* as = As + s*(128*GASTR);
        float* bs = Bs + s*(32*GBSTR);
        const int k0 = kt*32;
        #pragma unroll
        for (int i = 0; i < 4; i++){
            int r = (tid>>3) + i*32;
            cpa16(cvta_s(as + r*GASTR + (tid&7)*4), Ag + (size_t)r*K + k0 + (tid&7)*4);
        }
        #pragma unroll
        for (int i = 0; i < 4; i++){
            int r = (tid>>5) + i*8;
            cpa16(cvta_s(bs + r*GBSTR + (tid&31)*4), Bg + (size_t)(k0+r)*NB + (tid&31)*4);
        }
        CP_COMMIT();
    };

    load_stage(0, 0);
    for (int kt = 0; kt < KT; kt++){
        const int s = kt & 1;
        if (kt + 1 < KT){ load_stage(kt+1, s^1); CP_WAIT1(); }
        else            { CP_WAIT0(); }
        __syncthreads();
        const float* as = As + s*(128*GASTR);
        const float* bs = Bs + s*(32*GBSTR);
        #pragma unroll
        for (int kk = 0; kk < 4; kk++){
            uint32_t af[4][4], bf[4][2];
            const int kb = kk*8;
            #pragma unroll
            for (int mt = 0; mt < 4; mt++){
                const float* ap = as + (wm*64 + mt*16 + l4)*GASTR + kb + lk;
                af[mt][0] = tf32b(ap[0]);
                af[mt][1] = tf32b(ap[8*GASTR]);
                af[mt][2] = tf32b(ap[4]);
                af[mt][3] = tf32b(ap[8*GASTR+4]);
            }
            #pragma unroll
            for (int nt = 0; nt < 4; nt++){
                const float* bp = bs + (kb + lk)*GBSTR + wn*32 + nt*8 + l4;
                bf[nt][0] = tf32b(bp[0]);
                bf[nt][1] = tf32b(bp[4*GBSTR]);
            }
            #pragma unroll
            for (int mt = 0; mt < 4; mt++)
                #pragma unroll
                for (int nt = 0; nt < 4; nt++)
                    mma8(c[mt][nt], af[mt][0],af[mt][1],af[mt][2],af[mt][3],
                         bf[nt][0], bf[nt][1]);
        }
        __syncthreads();
    }

    #pragma unroll
    for (int mt = 0; mt < 4; mt++){
        const size_t r0 = (size_t)m_blk + wm*64 + mt*16 + l4;
        #pragma unroll
        for (int nt = 0; nt < 4; nt++){
            const size_t cc = (size_t)nC + wn*32 + nt*8 + lk*2;
            float2 v0 = make_float2(c[mt][nt][0], c[mt][nt][1]);
            float2 v1 = make_float2(c[mt][nt][2], c[mt][nt][3]);
            if (roundC){
                v0.x = tf32r(v0.x); v0.y = tf32r(v0.y);
                v1.x = tf32r(v1.x); v1.y = tf32r(v1.y);
            }
            *(float2*)(C + r0*NC + cc)     = v0;
            *(float2*)(C + (r0+8)*NC + cc) = v1;
        }
    }
}

// fused QKV projection: grid.x = 32 column-blocks over [Wq|Wk|Wv]
__global__ __launch_bounds__(256)
void gemm_qkv(const float* __restrict__ x,
              const float* __restrict__ Wq, const float* __restrict__ Wk,
              const float* __restrict__ Wv,
              float* __restrict__ q, float* __restrict__ k, float* __restrict__ v)
{
    extern __shared__ float gsm[];
    const int bxi = blockIdx.x;
    const int m_blk = blockIdx.y * 128;
    if (bxi < 16)
        gemm_body(x, Wq, q, Hx, QSTR, QSTR, 0, m_blk, bxi*128, bxi*128, gsm);
    else if (bxi < 24)
        gemm_body(x, Wk, k, Hx, KSTR, KSTR, 0, m_blk, (bxi-16)*128, (bxi-16)*128, gsm);
    else
        gemm_body(x, Wv, v, Hx, KSTR, KSTR, 1, m_blk, (bxi-24)*128, (bxi-24)*128, gsm);
}

// output projection
__global__ __launch_bounds__(256)
void gemm_wo(const float* __restrict__ att, const float* __restrict__ Wo,
             float* __restrict__ out)
{
    extern __shared__ float gsm[];
    gemm_body(att, Wo, out, QSTR, Hx, Hx, 0, blockIdx.y*128, blockIdx.x*128,
              blockIdx.x*128, gsm);
}

// ---------------- tf32 flash attention (R3 proven, 256 threads) --------------
#define AQS 260   /* Q / K smem row stride */
#define AVS 264   /* V smem row stride */
#define APS 68    /* P smem row stride */
#define ATT_SMEM ((64*AQS + 64*AVS + 64*APS + 3*64)*4)

__global__ __launch_bounds__(256)
void attn_tf32(const float* __restrict__ Q, const float* __restrict__ Kc,
               const float* __restrict__ Vc, float* __restrict__ O)
{
    extern __shared__ float att_sm[];
    float* sQ  = att_sm;
    float* sKV = sQ  + 64*AQS;
    float* sP  = sKV + 64*AVS;
    float* sM  = sP  + 64*APS;
    float* sL  = sM  + 64;
    float* sAl = sL  + 64;

    const int tid = threadIdx.x, warp = tid >> 5, lane = tid & 31;
    const int l4 = lane >> 2, lk = lane & 3;
    const int qt = blockIdx.x, h = blockIdx.y, b = blockIdx.z;
    const int q0 = qt * 64, kvh = h >> 1;
    const float* Qb = Q  + (size_t)(b*Tx)*QSTR + h*Dx;
    const float* Kb = Kc + (size_t)(b*Tx)*KSTR + kvh*Dx;
    const float* Vb = Vc + (size_t)(b*Tx)*KSTR + kvh*Dx;

    // Q tile (64 x 256) via cp.async
    #pragma unroll
    for (int i = 0; i < 16; i++){
        int idx = tid + i*256;
        int r = idx >> 6, c4 = idx & 63;
        cpa16(cvta_s(sQ + r*AQS + c4*4), Qb + (size_t)(q0+r)*QSTR + c4*4);
    }
    CP_COMMIT();
    if (tid < 64){ sM[tid] = -1e30f; sL[tid] = 0.f; }

    const int wms = warp >> 1, wns = warp & 1;   // S grid: 4m x 2n (warp 16x32)
    const int wmp = warp >> 2, wnp = warp & 3;   // PV grid: 2m x 4n (warp 32x64)

    float o[2][8][4];
    #pragma unroll
    for (int i = 0; i < 2; i++)
        #pragma unroll
        for (int j = 0; j < 8; j++)
            #pragma unroll
            for (int r = 0; r < 4; r++) o[i][j][r] = 0.f;

    const int kt0 = (qt > 16) ? qt - 16 : 0;
    for (int kt = kt0; kt <= qt; kt++){
        __syncthreads();                         // prev PV done with sKV
        #pragma unroll
        for (int i = 0; i < 16; i++){
            int idx = tid + i*256;
            int r = idx >> 6, c4 = idx & 63;
            cpa16(cvta_s(sKV + r*AQS + c4*4), Kb + (size_t)(kt*64+r)*KSTR + c4*4);
        }
        CP_COMMIT();
        CP_WAIT0();
        __syncthreads();

        // ---- S = Q K^T (tf32 mma) ----
        float s[4][4];
        #pragma unroll
        for (int nt = 0; nt < 4; nt++)
            #pragma unroll
            for (int r = 0; r < 4; r++) s[nt][r] = 0.f;

        #pragma unroll 4
        for (int d8 = 0; d8 < 32; d8++){
            const float* ap = sQ + (wms*16 + l4)*AQS + d8*8 + lk;
            uint32_t a0 = f2b(ap[0]), a1 = f2b(ap[8*AQS]);
            uint32_t a2 = f2b(ap[4]), a3 = f2b(ap[8*AQS+4]);
            #pragma unroll
            for (int nt = 0; nt < 4; nt++){
                const float* bp = sKV + (wns*32 + nt*8 + l4)*AQS + d8*8 + lk;
                mma8(s[nt], a0, a1, a2, a3, f2b(bp[0]), f2b(bp[4]));
            }
        }

        // mask + scale, store logits to sP
        #pragma unroll
        for (int nt = 0; nt < 4; nt++){
            const int cbase = wns*32 + nt*8 + lk*2;
            const int kg0 = kt*64 + cbase;
            #pragma unroll
            for (int half = 0; half < 2; half++){
                const int r  = wms*16 + l4 + half*8;
                const int qg = q0 + r;
                float2 v;
                v.x = (kg0   <= qg && qg - kg0     < WINDOWx) ? s[nt][half*2+0]*0.0625f : -1e30f;
                v.y = (kg0+1 <= qg && qg - (kg0+1) < WINDOWx) ? s[nt][half*2+1]*0.0625f : -1e30f;
                *(float2*)(sP + r*APS + cbase) = v;
            }
        }
        __syncthreads();

        // V tile cp.async (overlaps with softmax below)
        #pragma unroll
        for (int i = 0; i < 16; i++){
            int idx = tid + i*256;
            int r = idx >> 6, c4 = idx & 63;
            cpa16(cvta_s(sKV + r*AVS + c4*4), Vb + (size_t)(kt*64+r)*KSTR + c4*4);
        }
        CP_COMMIT();

        // ---- online softmax: 4 threads per row, 16 cols each ----
        {
            const int row = tid >> 2;
            const int cg  = (tid & 3) * 16;
            float* pr = sP + row*APS + cg;
            float4 p0 = *(float4*)(pr + 0);
            float4 p1 = *(float4*)(pr + 4);
            float4 p2 = *(float4*)(pr + 8);
            float4 p3 = *(float4*)(pr + 12);
            float rm = fmaxf(fmaxf(fmaxf(p0.x,p0.y),fmaxf(p0.z,p0.w)),
                             fmaxf(fmaxf(fmaxf(p1.x,p1.y),fmaxf(p1.z,p1.w)),
                             fmaxf(fmaxf(fmaxf(p2.x,p2.y),fmaxf(p2.z,p2.w)),
                                   fmaxf(fmaxf(p3.x,p3.y),fmaxf(p3.z,p3.w)))));
            rm = fmaxf(rm, __shfl_xor_sync(0xffffffffu, rm, 1));
            rm = fmaxf(rm, __shfl_xor_sync(0xffffffffu, rm, 2));
            const float mo = sM[row];
            const float mn = fmaxf(mo, rm);
            float rs = 0.f;
            #define AEXP(t) { t = (t > -1e29f) ? __expf(t - mn) : 0.f; rs += t; t = tf32r(t); }
            AEXP(p0.x); AEXP(p0.y); AEXP(p0.z); AEXP(p0.w);
            AEXP(p1.x); AEXP(p1.y); AEXP(p1.z); AEXP(p1.w);
            AEXP(p2.x); AEXP(p2.y); AEXP(p2.z); AEXP(p2.w);
            AEXP(p3.x); AEXP(p3.y); AEXP(p3.z); AEXP(p3.w);
            #undef AEXP
            *(float4*)(pr + 0)  = p0;
            *(float4*)(pr + 4)  = p1;
            *(float4*)(pr + 8)  = p2;
            *(float4*)(pr + 12) = p3;
            rs += __shfl_xor_sync(0xffffffffu, rs, 1);
            rs += __shfl_xor_sync(0xffffffffu, rs, 2);
            if ((tid & 3) == 0){
                float al = __expf(mo - mn);
                sAl[row] = al;
                sL[row]  = sL[row]*al + rs;
                sM[row]  = mn;
            }
        }
        CP_WAIT0();
        __syncthreads();

        // ---- O = alpha*O + P V ----
        const float a00 = sAl[wmp*32 + l4];
        const float a01 = sAl[wmp*32 + l4 + 8];
        const float a10 = sAl[wmp*32 + 16 + l4];
        const float a11 = sAl[wmp*32 + 16 + l4 + 8];
        #pragma unroll
        for (int nt = 0; nt < 8; nt++){
            o[0][nt][0]*=a00; o[0][nt][1]*=a00; o[0][nt][2]*=a01; o[0][nt][3]*=a01;
            o[1][nt][0]*=a10; o[1][nt][1]*=a10; o[1][nt][2]*=a11; o[1][nt][3]*=a11;
        }
        #pragma unroll
        for (int k8 = 0; k8 < 8; k8++){
            uint32_t af[2][4];
            #pragma unroll
            for (int mt = 0; mt < 2; mt++){
                const float* ap = sP + (wmp*32 + mt*16 + l4)*APS + k8*8 + lk;
                af[mt][0] = f2b(ap[0]);
                af[mt][1] = f2b(ap[8*APS]);
                af[mt][2] = f2b(ap[4]);
                af[mt][3] = f2b(ap[8*APS+4]);
            }
            #pragma unroll
            for (int nt = 0; nt < 8; nt++){
                const float* bp = sKV + (k8*8 + lk)*AVS + wnp*64 + nt*8 + l4;
                uint32_t b0 = f2b(bp[0]), b1 = f2b(bp[4*AVS]);
                #pragma unroll
                for (int mt = 0; mt < 2; mt++)
                    mma8(o[mt][nt], af[mt][0],af[mt][1],af[mt][2],af[mt][3], b0, b1);
            }
        }
    }

    // epilogue: normalize, round to tf32 (feeds Wo GEMM), write
    #pragma unroll
    for (int mt = 0; mt < 2; mt++){
        const int r0 = wmp*32 + mt*16 + l4;
        const float i0 = 1.0f / sL[r0];
        const float i1 = 1.0f / sL[r0+8];
        float* Ob0 = O + (size_t)(b*Tx + q0 + r0)*QSTR + h*Dx;
        float* Ob1 = O + (size_t)(b*Tx + q0 + r0 + 8)*QSTR + h*Dx;
        #pragma unroll
        for (int nt = 0; nt < 8; nt++){
            const int cc = wnp*64 + nt*8 + lk*2;
            float2 v0 = make_float2(tf32r(o[mt][nt][0]*i0), tf32r(o[mt][nt][1]*i0));
            float2 v1 = make_float2(tf32r(o[mt][nt][2]*i1), tf32r(o[mt][nt][3]*i1));
            *(float2*)(Ob0 + cc) = v0;
            *(float2*)(Ob1 + cc) = v1;
        }
    }
}

// ---------------- launch -----------------------------------------------------
extern "C" void kernel_launch(void* const* d_in, const int* in_sizes, int n_in,
                              void* d_out, int out_size)
{
    const float* x  = (const float*)d_in[0];
    const float* Wq = (const float*)d_in[1];
    const float* Wk = (const float*)d_in[2];
    const float* Wv = (const float*)d_in[3];
    const float* Wo = (const float*)d_in[4];
    const float* qs = (const float*)d_in[5];
    const float* ks = (const float*)d_in[6];
    const int*  seg = (const int*)d_in[7];
    const int*  cur = (n_in > 9) ? (const int*)d_in[9] : nullptr;
    float* out = (float*)d_out;
    (void)in_sizes; (void)out_size;

    float *q, *k, *v, *att, *pos;
    cudaGetSymbolAddress((void**)&q,   g_q);
    cudaGetSymbolAddress((void**)&k,   g_k);
    cudaGetSymbolAddress((void**)&v,   g_v);
    cudaGetSymbolAddress((void**)&att, g_att);
    cudaGetSymbolAddress((void**)&pos, g_pos);

    cudaFuncSetAttribute(gemm_qkv, cudaFuncAttributeMaxDynamicSharedMemorySize, GEMM_SMEM);
    cudaFuncSetAttribute(gemm_wo,  cudaFuncAttributeMaxDynamicSharedMemorySize, GEMM_SMEM);
    cudaFuncSetAttribute(attn_tf32, cudaFuncAttributeMaxDynamicSharedMemorySize, ATT_SMEM);

    pos_kernel<<<Bx, 256>>>(seg, cur, pos);

    gemm_qkv<<<dim3(32, NTOK/128), 256, GEMM_SMEM>>>(x, Wq, Wk, Wv, q, k, v);

    normrope_kernel<<<dim3(NTOK, NHx),  128>>>(q, qs, pos, QSTR);
    normrope_kernel<<<dim3(NTOK, NKVx), 128>>>(k, ks, pos, KSTR);

    attn_tf32<<<dim3(Tx/64, NHx, Bx), 256, ATT_SMEM>>>(q, k, v, att);

    gemm_wo<<<dim3(Hx/128, NTOK/128), 256, GEMM_SMEM>>>(att, Wo, out);
}